// round 11
// baseline (speedup 1.0000x reference)
#include <cuda_runtime.h>
#include <cstdint>

// Problem constants
#define BB 16
#define LL 512
#define DD 768
#define HH 12
#define UU 384
#define NH 6
#define HD 64
#define KP 384
#define RR 128        // L - K  (merged count == unpreserved count)
#define LH 256        // L/2
#define OT 386        // output tokens per batch

// ---------------- device scratch (static, allocation-free) ----------------
__device__ float              g_imp[BB * LL];
__device__ float              g_invn[BB * LL];
__device__ int                g_unp[BB * RR];
__device__ unsigned long long g_nodekey[BB * LH];
__device__ int                g_srctok[BB * RR];
__device__ int                g_dstj[BB * RR];
__device__ int                g_unm[BB * RR];
__device__ float              g_counts[BB * LH];
__device__ float              g_q[BB * UU];
__device__ float              g_m[BB * NH * DD];
__device__ float              g_cb[BB * NH];
__device__ float              g_logits[BB * NH * RR];
__device__ float              g_y[BB * NH * DD];
__device__ float              g_ctx[BB * UU];

__device__ __forceinline__ unsigned ford(float f) {
    unsigned u = __float_as_uint(f);
    return (u & 0x80000000u) ? ~u : (u | 0x80000000u);
}

// ---------------- K0: init accumulators (must run every replay) -----------
__global__ void k_init() {
    int i = blockIdx.x * blockDim.x + threadIdx.x;
    if (i < BB * LL) g_imp[i] = 0.f;
    if (i < BB * LH) { g_nodekey[i] = 0ull; g_counts[i] = 1.0f; }
}

// ---------------- K2: importance = column sums, diag removed --------------
// grid (8 row-chunks, 12 heads, 16 batch), 128 threads (4 cols each, float4)
__global__ void k_importance(const float* __restrict__ sc) {
    int b = blockIdx.z, h = blockIdx.y, chunk = blockIdx.x;
    int j0 = threadIdx.x * 4;
    const float* base = sc + (((size_t)b * HH + h) * LL + (size_t)chunk * 64) * LL;
    int i0 = chunk * 64;
    float a0 = 0.f, a1 = 0.f, a2 = 0.f, a3 = 0.f;
#pragma unroll 4
    for (int i = 0; i < 64; i++) {
        float4 v = *(const float4*)(base + (size_t)i * LL + j0);
        int gi = i0 + i;
        if (gi == j0)     v.x = 0.f;
        if (gi == j0 + 1) v.y = 0.f;
        if (gi == j0 + 2) v.z = 0.f;
        if (gi == j0 + 3) v.w = 0.f;
        a0 += v.x; a1 += v.y; a2 += v.z; a3 += v.w;
    }
    float* ip = g_imp + b * LL + j0;
    atomicAdd(ip + 0, a0); atomicAdd(ip + 1, a1);
    atomicAdd(ip + 2, a2); atomicAdd(ip + 3, a3);
}

// ---------------- K1: per-token inverse L2 norms ---------------------------
// grid (64, 16), 256 threads: one warp per row
__global__ void k_invnorm(const float* __restrict__ hid) {
    int warp = threadIdx.x >> 5, lane = threadIdx.x & 31;
    int row = blockIdx.x * 8 + warp;
    int b = blockIdx.y;
    const float4* p = (const float4*)(hid + ((size_t)b * LL + row) * DD);
    float s = 0.f;
#pragma unroll
    for (int it = 0; it < 6; it++) {
        float4 v = p[lane + it * 32];
        s += v.x * v.x + v.y * v.y + v.z * v.z + v.w * v.w;
    }
    for (int off = 16; off; off >>= 1) s += __shfl_xor_sync(0xffffffffu, s, off);
    if (lane == 0) g_invn[b * LL + row] = rsqrtf(s);
}

// ---------------- K3: top-K mask -> unpreserved idx (ascending) ------------
// grid 16, 512 threads. Rank-by-count with index tiebreak == lax.top_k.
__global__ void k_topk() {
    int b = blockIdx.x, t = threadIdx.x;
    __shared__ unsigned long long keys[LL];
    __shared__ int flags[LL];
    float v = g_imp[b * LL + t];
    unsigned long long key = ((unsigned long long)ford(v) << 32) | (unsigned)(0xFFFFFFFFu - t);
    keys[t] = key;
    __syncthreads();
    int rank = 0;
    for (int x = 0; x < LL; x++) rank += (keys[x] > key);
    int unp = (rank >= KP) ? 1 : 0;
    flags[t] = unp;
    __syncthreads();
    if (unp) {
        int pos = 0;
        for (int x = 0; x < t; x++) pos += flags[x];
        g_unp[b * RR + pos] = t;
    }
}

// ---------------- K4: cosine-sim GEMM + row max/argmax ---------------------
// C[i][j] = <na_i, nb_j>, a = even tokens, b = odd tokens, pre-normalized at
// smem-store time. 64x64 tile, 256 threads, 4x4 micro-tile (FP32 for exact
// rank preservation). Row argmax folded via packed atomicMax.
__global__ void k_sim(const float* __restrict__ hid) {
    int b = blockIdx.z, i0 = blockIdx.y * 64, j0 = blockIdx.x * 64;
    __shared__ float As[16][68];
    __shared__ float Bs[16][68];
    int tid = threadIdx.x;
    int tx = tid & 15, ty = tid >> 4;
    int lrow = tid >> 2, lseg = tid & 3;
    const float* base = hid + (size_t)b * LL * DD;
    float ia = g_invn[b * LL + 2 * (i0 + lrow)];
    float ib = g_invn[b * LL + 2 * (j0 + lrow) + 1];
    const float* arow = base + (size_t)(2 * (i0 + lrow)) * DD + lseg * 4;
    const float* brow = base + (size_t)(2 * (j0 + lrow) + 1) * DD + lseg * 4;

    float acc[4][4] = {};
    for (int k0 = 0; k0 < DD; k0 += 16) {
        float4 av = *(const float4*)(arow + k0);
        float4 bv = *(const float4*)(brow + k0);
        __syncthreads();
        As[lseg * 4 + 0][lrow] = av.x * ia;
        As[lseg * 4 + 1][lrow] = av.y * ia;
        As[lseg * 4 + 2][lrow] = av.z * ia;
        As[lseg * 4 + 3][lrow] = av.w * ia;
        Bs[lseg * 4 + 0][lrow] = bv.x * ib;
        Bs[lseg * 4 + 1][lrow] = bv.y * ib;
        Bs[lseg * 4 + 2][lrow] = bv.z * ib;
        Bs[lseg * 4 + 3][lrow] = bv.w * ib;
        __syncthreads();
#pragma unroll
        for (int kk = 0; kk < 16; kk++) {
            float a[4], c[4];
            *(float4*)a = *(const float4*)&As[kk][ty * 4];
            *(float4*)c = *(const float4*)&Bs[kk][tx * 4];
#pragma unroll
            for (int r = 0; r < 4; r++)
#pragma unroll
                for (int q = 0; q < 4; q++) acc[r][q] += a[r] * c[q];
        }
    }
    // per-row max/argmax (tie -> smaller j, matching jnp.argmax)
#pragma unroll
    for (int r = 0; r < 4; r++) {
        float best = acc[r][0]; int bc = 0;
        if (acc[r][1] > best) { best = acc[r][1]; bc = 1; }
        if (acc[r][2] > best) { best = acc[r][2]; bc = 2; }
        if (acc[r][3] > best) { best = acc[r][3]; bc = 3; }
        int j = j0 + tx * 4 + bc;
        unsigned long long key = ((unsigned long long)ford(best) << 32) | (unsigned)(255 - j);
        for (int off = 8; off; off >>= 1) {
            unsigned long long o = __shfl_xor_sync(0xffffffffu, key, off);
            if (o > key) key = o;
        }
        if (tx == 0) atomicMax(&g_nodekey[b * LH + i0 + ty * 4 + r], key);
    }
}

// ---------------- K5: stable descending edge argsort via rank counting -----
// grid 16, 256 threads. rank<128 -> src (position = rank), else unm.
__global__ void k_edges() {
    int b = blockIdx.x, i = threadIdx.x;
    __shared__ unsigned long long ek[LH];
    unsigned long long nk = g_nodekey[b * LH + i];
    int nidx = 255 - (int)(unsigned)(nk & 0xFFFFFFFFull);
    unsigned long long key = (nk & 0xFFFFFFFF00000000ull) | (unsigned)(255 - i);
    ek[i] = key;
    __syncthreads();
    int rank = 0;
    for (int x = 0; x < LH; x++) rank += (ek[x] > key);
    if (rank < RR) {
        g_srctok[b * RR + rank] = i;
        g_dstj[b * RR + rank] = nidx;
        atomicAdd(&g_counts[b * LH + nidx], 1.0f);
    } else {
        g_unm[b * RR + (rank - RR)] = i;
    }
}

// ---------------- K6: assemble output ---------------------------------------
__global__ void k_zero_dst(float* __restrict__ out) {
    int b = blockIdx.y, j = blockIdx.x;
    ((float4*)(out + ((size_t)b * OT + 129 + j) * DD))[threadIdx.x] = make_float4(0.f, 0.f, 0.f, 0.f);
}

__global__ void k_copy(const float* __restrict__ hid, float* __restrict__ out) {
    int b = blockIdx.y, v = blockIdx.x;                  // 0..128
    int srow = (v == 0) ? 0 : 2 * g_unm[b * RR + (v - 1)];
    const float4* s = (const float4*)(hid + ((size_t)b * LL + srow) * DD);
    float4* d = (float4*)(out + ((size_t)b * OT + v) * DD);
    d[threadIdx.x] = s[threadIdx.x];
}

__global__ void k_scatter(const float* __restrict__ hid, float* __restrict__ out) {
    int b = blockIdx.y, p = blockIdx.x;                  // 0..127
    int s = g_srctok[b * RR + p], dj = g_dstj[b * RR + p];
    const float* src = hid + ((size_t)b * LL + 2 * s) * DD;
    float* dst = out + ((size_t)b * OT + 129 + dj) * DD;
    int d0 = threadIdx.x * 4;
    float4 v = *(const float4*)(src + d0);
    atomicAdd(dst + d0 + 0, v.x);
    atomicAdd(dst + d0 + 1, v.y);
    atomicAdd(dst + d0 + 2, v.z);
    atomicAdd(dst + d0 + 3, v.w);
}

__global__ void k_merge(const float* __restrict__ hid, float* __restrict__ out) {
    int b = blockIdx.y, j = blockIdx.x;                  // 0..255
    float c = g_counts[b * LH + j];
    int d0 = threadIdx.x * 4;
    float* o = out + ((size_t)b * OT + 129 + j) * DD + d0;
    float4 a = *(float4*)o;
    float4 x = *(const float4*)(hid + ((size_t)b * LL + 2 * j + 1) * DD + d0);
    a.x = (a.x + x.x) / c; a.y = (a.y + x.y) / c;
    a.z = (a.z + x.z) / c; a.w = (a.w + x.w) / c;
    *(float4*)o = a;
}

// ---------------- attention (refactored) ------------------------------------
// q = cls @ Wq + bq        grid 16, 384 threads
__global__ void k_q(const float* __restrict__ hid, const float* __restrict__ Wq,
                    const float* __restrict__ bq) {
    int b = blockIdx.x, u = threadIdx.x;
    __shared__ float cls[DD];
    cls[u] = hid[(size_t)b * LL * DD + u];
    cls[u + UU] = hid[(size_t)b * LL * DD + UU + u];
    __syncthreads();
    float a0 = bq[u], a1 = 0.f;
#pragma unroll 4
    for (int k = 0; k < DD; k += 2) {
        a0 += cls[k] * Wq[(size_t)k * UU + u];
        a1 += cls[k + 1] * Wq[(size_t)(k + 1) * UU + u];
    }
    g_q[b * UU + u] = a0 + a1;
}

// m[b,h,:] = Wk_h @ q_h ; cbias = q_h . bk_h     grid (6,16), 768 threads
__global__ void k_m(const float* __restrict__ Wk, const float* __restrict__ bk) {
    int h = blockIdx.x, b = blockIdx.y, t = threadIdx.x;
    __shared__ float sq[HD];
    __shared__ float sp[HD];
    if (t < HD) sq[t] = g_q[b * UU + h * HD + t];
    __syncthreads();
    float acc = 0.f;
    const float* wrow = Wk + (size_t)t * UU + h * HD;
#pragma unroll
    for (int u = 0; u < HD; u += 4) {
        float4 wv = *(const float4*)(wrow + u);
        acc += wv.x * sq[u] + wv.y * sq[u + 1] + wv.z * sq[u + 2] + wv.w * sq[u + 3];
    }
    g_m[((size_t)b * NH + h) * DD + t] = acc;
    if (t < HD) sp[t] = sq[t] * bk[h * HD + t];
    __syncthreads();
    if (t == 0) {
        float c = 0.f;
        for (int u = 0; u < HD; u++) c += sp[u];
        g_cb[b * NH + h] = c;
    }
}

// logits[b,h,t] = (x_t . m_bh + cbias) / 8      one warp per (b,t)
__global__ void k_logits(const float* __restrict__ hid) {
    int w = (blockIdx.x * blockDim.x + threadIdx.x) >> 5;
    int lane = threadIdx.x & 31;
    if (w >= BB * RR) return;
    int b = w >> 7, t = w & 127;
    int row = g_unp[b * RR + t];
    const float* x = hid + ((size_t)b * LL + row) * DD;
    const float* m = g_m + (size_t)b * NH * DD;
    float acc[NH] = {};
    for (int k = lane; k < DD; k += 32) {
        float xv = x[k];
#pragma unroll
        for (int h = 0; h < NH; h++) acc[h] += xv * m[h * DD + k];
    }
#pragma unroll
    for (int h = 0; h < NH; h++)
        for (int off = 16; off; off >>= 1) acc[h] += __shfl_xor_sync(0xffffffffu, acc[h], off);
    if (lane == 0) {
#pragma unroll
        for (int h = 0; h < NH; h++)
            g_logits[((size_t)b * NH + h) * RR + t] = (acc[h] + g_cb[b * NH + h]) * 0.125f;
    }
}

// softmax over 128 keys, then y[b,h,:] = sum_t w_t * x_t   grid (6,16), 256 thr
__global__ void k_smax_y(const float* __restrict__ hid) {
    int h = blockIdx.x, b = blockIdx.y, t = threadIdx.x;
    __shared__ float w[RR];
    __shared__ int su[RR];
    __shared__ float red[8];
    if (t < RR) {
        w[t] = g_logits[((size_t)b * NH + h) * RR + t];
        su[t] = g_unp[b * RR + t];
    }
    __syncthreads();
    if (t < RR) {
        float m = w[t];
        for (int off = 16; off; off >>= 1) m = fmaxf(m, __shfl_xor_sync(0xffffffffu, m, off));
        if ((t & 31) == 0) red[t >> 5] = m;
    }
    __syncthreads();
    float mx = fmaxf(fmaxf(red[0], red[1]), fmaxf(red[2], red[3]));
    float e = 0.f;
    if (t < RR) e = expf(w[t] - mx);
    float s = e;
    for (int off = 16; off; off >>= 1) s += __shfl_xor_sync(0xffffffffu, s, off);
    if (t < RR && (t & 31) == 0) red[4 + (t >> 5)] = s;
    __syncthreads();
    float tot = red[4] + red[5] + red[6] + red[7];
    if (t < RR) w[t] = e / tot;
    __syncthreads();
    for (int d = t; d < DD; d += 256) {
        float acc = 0.f;
#pragma unroll 4
        for (int tt = 0; tt < RR; tt++)
            acc += w[tt] * hid[((size_t)b * LL + su[tt]) * DD + d];
        g_y[((size_t)b * NH + h) * DD + d] = acc;
    }
}

// ctx[b,u] = y[b,h(u),:] . Wv[:,u] + bv[u]    grid 16, 384 threads
__global__ void k_ctx(const float* __restrict__ Wv, const float* __restrict__ bv) {
    int b = blockIdx.x, u = threadIdx.x;
    __shared__ float sy[NH * DD];
    for (int i = u; i < NH * DD; i += UU) sy[i] = g_y[(size_t)b * NH * DD + i];
    __syncthreads();
    int h = u >> 6;
    float acc = bv[u];
#pragma unroll 4
    for (int d = 0; d < DD; d++) acc += sy[h * DD + d] * Wv[(size_t)d * UU + u];
    g_ctx[b * UU + u] = acc;
}

// new_token = ctx @ Wo + bo -> out row 385    grid 16, 768 threads
__global__ void k_newtok(const float* __restrict__ Wo, const float* __restrict__ bo,
                         float* __restrict__ out) {
    int b = blockIdx.x, d = threadIdx.x;
    __shared__ float sc[UU];
    if (d < UU) sc[d] = g_ctx[b * UU + d];
    __syncthreads();
    float acc = bo[d];
#pragma unroll 4
    for (int u = 0; u < UU; u++) acc += sc[u] * Wo[(size_t)u * DD + d];
    out[((size_t)b * OT + 385) * DD + d] = acc;
}

// ---------------- launch ----------------------------------------------------
extern "C" void kernel_launch(void* const* d_in, const int* in_sizes, int n_in,
                              void* d_out, int out_size) {
    (void)in_sizes; (void)n_in; (void)out_size;
    const float* hid = (const float*)d_in[0];
    const float* sc  = (const float*)d_in[1];
    const float* Wq  = (const float*)d_in[2];
    const float* bq  = (const float*)d_in[3];
    const float* Wk  = (const float*)d_in[4];
    const float* bk  = (const float*)d_in[5];
    const float* Wv  = (const float*)d_in[6];
    const float* bv  = (const float*)d_in[7];
    const float* Wo  = (const float*)d_in[8];
    const float* bo  = (const float*)d_in[9];
    float* out = (float*)d_out;

    k_init<<<32, 256>>>();
    k_importance<<<dim3(8, HH, BB), 128>>>(sc);
    k_invnorm<<<dim3(64, BB), 256>>>(hid);
    k_topk<<<BB, 512>>>();
    k_sim<<<dim3(4, 4, BB), 256>>>(hid);
    k_edges<<<BB, 256>>>();
    k_zero_dst<<<dim3(LH, BB), 192>>>(out);
    k_copy<<<dim3(129, BB), 192>>>(hid, out);
    k_scatter<<<dim3(RR, BB), 192>>>(hid, out);
    k_merge<<<dim3(LH, BB), 192>>>(hid, out);
    k_q<<<BB, UU>>>(hid, Wq, bq);
    k_m<<<dim3(NH, BB), DD>>>(Wk, bk);
    k_logits<<<256, 256>>>(hid);
    k_smax_y<<<dim3(NH, BB), 256>>>(hid);
    k_ctx<<<BB, UU>>>(Wv, bv);
    k_newtok<<<BB, DD>>>(Wo, bo, out);
}

// round 12
// speedup vs baseline: 1.3610x; 1.3610x over previous
#include <cuda_runtime.h>
#include <cstdint>

// Problem constants
#define BB 16
#define LL 512
#define DD 768
#define HH 12
#define UU 384
#define NH 6
#define HD 64
#define KP 384
#define RR 128        // L - K  (merged count == unpreserved count)
#define LH 256        // L/2
#define OT 386        // output tokens per batch

// ---------------- device scratch (static, allocation-free) ----------------
__device__ float              g_imp[BB * LL];
__device__ float              g_invn[BB * LL];
__device__ int                g_unp[BB * RR];
__device__ unsigned long long g_nodekey[BB * LH];
__device__ int                g_unm[BB * RR];
__device__ int                g_csr_off[BB * (LH + 1)];
__device__ int                g_csr_src[BB * RR];
__device__ float              g_m[BB * NH * DD];
__device__ float              g_cb[BB * NH];
__device__ float              g_logits[BB * NH * RR];
__device__ float              g_y[BB * NH * DD];
__device__ float              g_ctxp[4][BB * UU];

__device__ __forceinline__ unsigned ford(float f) {
    unsigned u = __float_as_uint(f);
    return (u & 0x80000000u) ? ~u : (u | 0x80000000u);
}

// packed fp32x2 FMA (sm_100+): acc = a*b + acc, two lanes per instruction
__device__ __forceinline__ void ffma2(unsigned long long& acc,
                                      unsigned long long a, unsigned long long b) {
    asm("fma.rn.f32x2 %0, %1, %2, %0;" : "+l"(acc) : "l"(a), "l"(b));
}
__device__ __forceinline__ unsigned long long pk2(float x, float y) {
    unsigned long long r;
    asm("mov.b64 %0, {%1, %2};" : "=l"(r) : "f"(x), "f"(y));
    return r;
}
__device__ __forceinline__ float lo32(unsigned long long v) {
    return __uint_as_float((unsigned)v);
}
__device__ __forceinline__ float hi32(unsigned long long v) {
    return __uint_as_float((unsigned)(v >> 32));
}

// ---------------- K0: init accumulators (must run every replay) -----------
__global__ void k_init() {
    int i = blockIdx.x * blockDim.x + threadIdx.x;
    if (i < BB * LL) g_imp[i] = 0.f;
    if (i < BB * LH) g_nodekey[i] = 0ull;
}

// ---------------- importance = column sums, diag removed ------------------
__global__ void k_importance(const float* __restrict__ sc) {
    int b = blockIdx.z, h = blockIdx.y, chunk = blockIdx.x;
    int j0 = threadIdx.x * 4;
    const float* base = sc + (((size_t)b * HH + h) * LL + (size_t)chunk * 64) * LL;
    int i0 = chunk * 64;
    float a0 = 0.f, a1 = 0.f, a2 = 0.f, a3 = 0.f;
#pragma unroll 4
    for (int i = 0; i < 64; i++) {
        float4 v = *(const float4*)(base + (size_t)i * LL + j0);
        int gi = i0 + i;
        if (gi == j0)     v.x = 0.f;
        if (gi == j0 + 1) v.y = 0.f;
        if (gi == j0 + 2) v.z = 0.f;
        if (gi == j0 + 3) v.w = 0.f;
        a0 += v.x; a1 += v.y; a2 += v.z; a3 += v.w;
    }
    float* ip = g_imp + b * LL + j0;
    atomicAdd(ip + 0, a0); atomicAdd(ip + 1, a1);
    atomicAdd(ip + 2, a2); atomicAdd(ip + 3, a3);
}

// ---------------- per-token inverse L2 norms -------------------------------
__global__ void k_invnorm(const float* __restrict__ hid) {
    int warp = threadIdx.x >> 5, lane = threadIdx.x & 31;
    int row = blockIdx.x * 8 + warp;
    int b = blockIdx.y;
    const float4* p = (const float4*)(hid + ((size_t)b * LL + row) * DD);
    float s = 0.f;
#pragma unroll
    for (int it = 0; it < 6; it++) {
        float4 v = p[lane + it * 32];
        s += v.x * v.x + v.y * v.y + v.z * v.z + v.w * v.w;
    }
    for (int off = 16; off; off >>= 1) s += __shfl_xor_sync(0xffffffffu, s, off);
    if (lane == 0) g_invn[b * LL + row] = rsqrtf(s);
}

// ---------------- top-K -> unpreserved idx (ascending) ---------------------
// Rank-by-count with index tiebreak == lax.top_k; ballot-based compaction.
__global__ void k_topk() {
    int b = blockIdx.x, t = threadIdx.x;
    __shared__ __align__(16) unsigned long long keys[LL];
    __shared__ int wsum[16];
    float v = g_imp[b * LL + t];
    unsigned long long key =
        ((unsigned long long)ford(v) << 32) | (unsigned)(0xFFFFFFFFu - t);
    keys[t] = key;
    __syncthreads();
    int rank = 0;
    const ulonglong2* k2 = (const ulonglong2*)keys;
#pragma unroll 8
    for (int x = 0; x < LL / 2; x++) {
        ulonglong2 kk = k2[x];
        rank += (kk.x > key) + (kk.y > key);
    }
    int unp = (rank >= KP) ? 1 : 0;
    unsigned bal = __ballot_sync(0xffffffffu, unp);
    int lane = t & 31, wp = t >> 5;
    if (lane == 0) wsum[wp] = __popc(bal);
    __syncthreads();
    if (unp) {
        int base = 0;
        for (int w = 0; w < wp; w++) base += wsum[w];
        int pos = base + __popc(bal & ((1u << lane) - 1));
        g_unp[b * RR + pos] = t;
    }
}

// ---------------- cosine-sim GEMM + row max/argmax -------------------------
// 64x64 tile, 256 threads, 4x4 micro-tile in packed fp32x2 (exact fp32 fma
// per element — rank decisions identical to scalar). Row argmax via atomicMax.
__global__ void k_sim(const float* __restrict__ hid) {
    int b = blockIdx.z, i0 = blockIdx.y * 64, j0 = blockIdx.x * 64;
    __shared__ __align__(16) float As[16][68];
    __shared__ __align__(16) float Bs[16][68];
    int tid = threadIdx.x;
    int tx = tid & 15, ty = tid >> 4;
    int lrow = tid >> 2, lseg = tid & 3;
    const float* base = hid + (size_t)b * LL * DD;
    float ia = g_invn[b * LL + 2 * (i0 + lrow)];
    float ib = g_invn[b * LL + 2 * (j0 + lrow) + 1];
    const float* arow = base + (size_t)(2 * (i0 + lrow)) * DD + lseg * 4;
    const float* brow = base + (size_t)(2 * (j0 + lrow) + 1) * DD + lseg * 4;

    // acc2[p][q]: p=0 packs rows (4ty, 4ty+1), p=1 packs rows (4ty+2, 4ty+3)
    unsigned long long acc2[2][4];
#pragma unroll
    for (int p = 0; p < 2; p++)
#pragma unroll
        for (int q = 0; q < 4; q++) acc2[p][q] = 0ull;

    for (int k0 = 0; k0 < DD; k0 += 16) {
        float4 av = *(const float4*)(arow + k0);
        float4 bv = *(const float4*)(brow + k0);
        __syncthreads();
        As[lseg * 4 + 0][lrow] = av.x * ia;
        As[lseg * 4 + 1][lrow] = av.y * ia;
        As[lseg * 4 + 2][lrow] = av.z * ia;
        As[lseg * 4 + 3][lrow] = av.w * ia;
        Bs[lseg * 4 + 0][lrow] = bv.x * ib;
        Bs[lseg * 4 + 1][lrow] = bv.y * ib;
        Bs[lseg * 4 + 2][lrow] = bv.z * ib;
        Bs[lseg * 4 + 3][lrow] = bv.w * ib;
        __syncthreads();
#pragma unroll
        for (int kk = 0; kk < 16; kk++) {
            ulonglong2 ap = *(const ulonglong2*)&As[kk][ty * 4];  // (a0,a1),(a2,a3)
            float4 c4 = *(const float4*)&Bs[kk][tx * 4];
            unsigned long long c0 = pk2(c4.x, c4.x);
            unsigned long long c1 = pk2(c4.y, c4.y);
            unsigned long long c2 = pk2(c4.z, c4.z);
            unsigned long long c3 = pk2(c4.w, c4.w);
            ffma2(acc2[0][0], ap.x, c0); ffma2(acc2[1][0], ap.y, c0);
            ffma2(acc2[0][1], ap.x, c1); ffma2(acc2[1][1], ap.y, c1);
            ffma2(acc2[0][2], ap.x, c2); ffma2(acc2[1][2], ap.y, c2);
            ffma2(acc2[0][3], ap.x, c3); ffma2(acc2[1][3], ap.y, c3);
        }
    }
    // per-row max/argmax (tie -> smaller j, matching jnp.argmax)
#pragma unroll
    for (int r = 0; r < 4; r++) {
        int p = r >> 1;
        float v0, v1, v2, v3;
        if (r & 1) {
            v0 = hi32(acc2[p][0]); v1 = hi32(acc2[p][1]);
            v2 = hi32(acc2[p][2]); v3 = hi32(acc2[p][3]);
        } else {
            v0 = lo32(acc2[p][0]); v1 = lo32(acc2[p][1]);
            v2 = lo32(acc2[p][2]); v3 = lo32(acc2[p][3]);
        }
        float best = v0; int bc = 0;
        if (v1 > best) { best = v1; bc = 1; }
        if (v2 > best) { best = v2; bc = 2; }
        if (v3 > best) { best = v3; bc = 3; }
        int j = j0 + tx * 4 + bc;
        unsigned long long key =
            ((unsigned long long)ford(best) << 32) | (unsigned)(255 - j);
        for (int off = 8; off; off >>= 1) {
            unsigned long long o = __shfl_xor_sync(0xffffffffu, key, off);
            if (o > key) key = o;
        }
        if (tx == 0) atomicMax(&g_nodekey[b * LH + i0 + ty * 4 + r], key);
    }
}

// ---------------- edge argsort + CSR inverse map ---------------------------
// rank<128 -> src (build dst->src CSR lists in smem), else unm.
__global__ void k_edges() {
    int b = blockIdx.x, i = threadIdx.x;
    __shared__ __align__(16) unsigned long long ek[LH];
    __shared__ int scnt[LH];
    __shared__ int soff[LH];
    __shared__ int scur[LH];
    unsigned long long nk = g_nodekey[b * LH + i];
    int nidx = 255 - (int)(unsigned)(nk & 0xFFFFFFFFull);
    unsigned long long key = (nk & 0xFFFFFFFF00000000ull) | (unsigned)(255 - i);
    ek[i] = key;
    scnt[i] = 0;
    scur[i] = 0;
    __syncthreads();
    int rank = 0;
    const ulonglong2* k2 = (const ulonglong2*)ek;
#pragma unroll 8
    for (int x = 0; x < LH / 2; x++) {
        ulonglong2 kk = k2[x];
        rank += (kk.x > key) + (kk.y > key);
    }
    bool issrc = (rank < RR);
    if (issrc) atomicAdd(&scnt[nidx], 1);
    else g_unm[b * RR + (rank - RR)] = i;
    __syncthreads();
    int off = 0;
    for (int x = 0; x < i; x++) off += scnt[x];
    soff[i] = off;
    g_csr_off[b * (LH + 1) + i] = off;
    if (i == 0) g_csr_off[b * (LH + 1) + LH] = RR;
    __syncthreads();
    if (issrc) {
        int slot = atomicAdd(&scur[nidx], 1);
        g_csr_src[b * RR + soff[nidx] + slot] = i;
    }
}

// ---------------- assemble: class + unm copies -----------------------------
__global__ void k_copy(const float* __restrict__ hid, float* __restrict__ out) {
    int b = blockIdx.y, v = blockIdx.x;                  // 0..128
    int srow = (v == 0) ? 0 : 2 * g_unm[b * RR + (v - 1)];
    const float4* s = (const float4*)(hid + ((size_t)b * LL + srow) * DD);
    float4* d = (float4*)(out + ((size_t)b * OT + v) * DD);
    d[threadIdx.x] = s[threadIdx.x];
}

// ---------------- merged dst tokens via CSR gather (no atomics) ------------
__global__ void k_merge2(const float* __restrict__ hid, float* __restrict__ out) {
    int b = blockIdx.y, j = blockIdx.x;                  // 0..255
    int o0 = g_csr_off[b * (LH + 1) + j];
    int o1 = g_csr_off[b * (LH + 1) + j + 1];
    int d0 = threadIdx.x * 4;
    const float* dx = hid + ((size_t)b * LL + 2 * j + 1) * DD + d0;
    float4 a = *(const float4*)dx;
    for (int p = o0; p < o1; p++) {
        int s = g_csr_src[b * RR + p];
        float4 v = *(const float4*)(hid + ((size_t)b * LL + 2 * s) * DD + d0);
        a.x += v.x; a.y += v.y; a.z += v.z; a.w += v.w;
    }
    float inv = 1.0f / (float)(1 + (o1 - o0));
    a.x *= inv; a.y *= inv; a.z *= inv; a.w *= inv;
    *(float4*)(out + ((size_t)b * OT + 129 + j) * DD + d0) = a;
}

// ---------------- attention: q_h + m_h + cbias fused, grid (6,16) ----------
__global__ void k_qm(const float* __restrict__ hid, const float* __restrict__ Wq,
                     const float* __restrict__ bq, const float* __restrict__ Wk,
                     const float* __restrict__ bk) {
    int h = blockIdx.x, b = blockIdx.y, t = threadIdx.x;     // 256 threads
    __shared__ float cls[DD];
    __shared__ float qp[4][HD];
    __shared__ float sq[HD];
    __shared__ float sp[HD];
    cls[t] = hid[(size_t)b * LL * DD + t];
    cls[t + 256] = hid[(size_t)b * LL * DD + 256 + t];
    cls[t + 512] = hid[(size_t)b * LL * DD + 512 + t];
    __syncthreads();
    // stage 1: q_h[u] = bq + cls . Wq[:, h*64+u], k split 4 ways
    {
        int u = t & 63, kq = t >> 6;
        float p = 0.f;
        const float* wcol = Wq + (size_t)(h * HD + u);
#pragma unroll 4
        for (int k = kq * 192; k < kq * 192 + 192; k++)
            p += cls[k] * wcol[(size_t)k * UU];
        qp[kq][u] = p;
    }
    __syncthreads();
    if (t < HD) {
        float q = bq[h * HD + t] + qp[0][t] + qp[1][t] + qp[2][t] + qp[3][t];
        sq[t] = q;
        sp[t] = q * bk[h * HD + t];
    }
    __syncthreads();
    // stage 2: m[row] = Wk[row, h*64:h*64+64] . q_h, rows t, t+256, t+512
#pragma unroll
    for (int rr = 0; rr < 3; rr++) {
        int row = t + rr * 256;
        const float* wrow = Wk + (size_t)row * UU + h * HD;
        float acc = 0.f;
#pragma unroll
        for (int u = 0; u < HD; u += 4) {
            float4 wv = *(const float4*)(wrow + u);
            acc += wv.x * sq[u] + wv.y * sq[u + 1] + wv.z * sq[u + 2] + wv.w * sq[u + 3];
        }
        g_m[((size_t)b * NH + h) * DD + row] = acc;
    }
    if (t == 0) {
        float c = 0.f;
        for (int u = 0; u < HD; u++) c += sp[u];
        g_cb[b * NH + h] = c;
    }
}

// logits[b,h,t] = (x_t . m_bh + cbias) / 8      one warp per (b,t)
__global__ void k_logits(const float* __restrict__ hid) {
    int w = (blockIdx.x * blockDim.x + threadIdx.x) >> 5;
    int lane = threadIdx.x & 31;
    if (w >= BB * RR) return;
    int b = w >> 7, t = w & 127;
    int row = g_unp[b * RR + t];
    const float* x = hid + ((size_t)b * LL + row) * DD;
    const float* m = g_m + (size_t)b * NH * DD;
    float acc[NH] = {};
    for (int k = lane; k < DD; k += 32) {
        float xv = x[k];
#pragma unroll
        for (int h = 0; h < NH; h++) acc[h] += xv * m[h * DD + k];
    }
#pragma unroll
    for (int h = 0; h < NH; h++)
        for (int off = 16; off; off >>= 1) acc[h] += __shfl_xor_sync(0xffffffffu, acc[h], off);
    if (lane == 0) {
#pragma unroll
        for (int h = 0; h < NH; h++)
            g_logits[((size_t)b * NH + h) * RR + t] = (acc[h] + g_cb[b * NH + h]) * 0.125f;
    }
}

// softmax over 128 keys, then y[b,h,:] = sum_t w_t * x_t   grid (6,16), 256 thr
__global__ void k_smax_y(const float* __restrict__ hid) {
    int h = blockIdx.x, b = blockIdx.y, t = threadIdx.x;
    __shared__ float w[RR];
    __shared__ int su[RR];
    __shared__ float red[8];
    if (t < RR) {
        w[t] = g_logits[((size_t)b * NH + h) * RR + t];
        su[t] = g_unp[b * RR + t];
    }
    __syncthreads();
    if (t < RR) {
        float m = w[t];
        for (int off = 16; off; off >>= 1) m = fmaxf(m, __shfl_xor_sync(0xffffffffu, m, off));
        if ((t & 31) == 0) red[t >> 5] = m;
    }
    __syncthreads();
    float mx = fmaxf(fmaxf(red[0], red[1]), fmaxf(red[2], red[3]));
    float e = 0.f;
    if (t < RR) e = expf(w[t] - mx);
    float s = e;
    for (int off = 16; off; off >>= 1) s += __shfl_xor_sync(0xffffffffu, s, off);
    if (t < RR && (t & 31) == 0) red[4 + (t >> 5)] = s;
    __syncthreads();
    float tot = red[4] + red[5] + red[6] + red[7];
    if (t < RR) w[t] = e / tot;
    __syncthreads();
    for (int d = t; d < DD; d += 256) {
        float acc = 0.f;
#pragma unroll 4
        for (int tt = 0; tt < RR; tt++)
            acc += w[tt] * hid[((size_t)b * LL + su[tt]) * DD + d];
        g_y[((size_t)b * NH + h) * DD + d] = acc;
    }
}

// ctx partials: grid (16, 4), 384 threads; chunk c covers 192 of the 768 d's.
__global__ void k_ctx(const float* __restrict__ Wv, const float* __restrict__ bv) {
    int b = blockIdx.x, c = blockIdx.y, u = threadIdx.x;
    __shared__ float sy[NH * 192];
    for (int i = u; i < NH * 192; i += UU) {
        int h = i / 192, dd = i % 192;
        sy[i] = g_y[((size_t)b * NH + h) * DD + c * 192 + dd];
    }
    __syncthreads();
    int h = u >> 6;
    float acc = (c == 0) ? bv[u] : 0.f;
    const float* wv = Wv + (size_t)(c * 192) * UU + u;
#pragma unroll 4
    for (int dd = 0; dd < 192; dd++) acc += sy[h * 192 + dd] * wv[(size_t)dd * UU];
    g_ctxp[c][b * UU + u] = acc;
}

// new_token: grid (16, 6), 128 threads; sums 4 ctx partials, then GEMV.
__global__ void k_newtok(const float* __restrict__ Wo, const float* __restrict__ bo,
                         float* __restrict__ out) {
    int b = blockIdx.x, seg = blockIdx.y, t = threadIdx.x;
    __shared__ float sc[UU];
    for (int i = t; i < UU; i += 128)
        sc[i] = g_ctxp[0][b * UU + i] + g_ctxp[1][b * UU + i] +
                g_ctxp[2][b * UU + i] + g_ctxp[3][b * UU + i];
    __syncthreads();
    int d = seg * 128 + t;
    float acc = bo[d];
#pragma unroll 4
    for (int u = 0; u < UU; u++) acc += sc[u] * Wo[(size_t)u * DD + d];
    out[((size_t)b * OT + 385) * DD + d] = acc;
}

// ---------------- launch ----------------------------------------------------
extern "C" void kernel_launch(void* const* d_in, const int* in_sizes, int n_in,
                              void* d_out, int out_size) {
    (void)in_sizes; (void)n_in; (void)out_size;
    const float* hid = (const float*)d_in[0];
    const float* sc  = (const float*)d_in[1];
    const float* Wq  = (const float*)d_in[2];
    const float* bq  = (const float*)d_in[3];
    const float* Wk  = (const float*)d_in[4];
    const float* bk  = (const float*)d_in[5];
    const float* Wv  = (const float*)d_in[6];
    const float* bv  = (const float*)d_in[7];
    const float* Wo  = (const float*)d_in[8];
    const float* bo  = (const float*)d_in[9];
    float* out = (float*)d_out;

    k_init<<<32, 256>>>();
    k_importance<<<dim3(8, HH, BB), 128>>>(sc);
    k_invnorm<<<dim3(64, BB), 256>>>(hid);
    k_topk<<<BB, 512>>>();
    k_sim<<<dim3(4, 4, BB), 256>>>(hid);
    k_edges<<<BB, 256>>>();
    k_copy<<<dim3(129, BB), 192>>>(hid, out);
    k_merge2<<<dim3(LH, BB), 192>>>(hid, out);
    k_qm<<<dim3(NH, BB), 256>>>(hid, Wq, bq, Wk, bk);
    k_logits<<<256, 256>>>(hid);
    k_smax_y<<<dim3(NH, BB), 256>>>(hid);
    k_ctx<<<dim3(BB, 4), 384>>>(Wv, bv);
    k_newtok<<<dim3(BB, 6), 128>>>(Wo, bo, out);
}

// round 13
// speedup vs baseline: 1.3639x; 1.0021x over previous
#include <cuda_runtime.h>
#include <cstdint>

// Problem constants
#define BB 16
#define LL 512
#define DD 768
#define HH 12
#define UU 384
#define NH 6
#define HD 64
#define KP 384
#define RR 128        // L - K  (merged count == unpreserved count)
#define LH 256        // L/2
#define OT 386        // output tokens per batch

// ---------------- device scratch (static, allocation-free) ----------------
__device__ float              g_imp[BB * LL];
__device__ float              g_invn[BB * LL];
__device__ int                g_unp[BB * RR];
__device__ unsigned long long g_nodekey[BB * LH];
__device__ int                g_unm[BB * RR];
__device__ int                g_csr_off[BB * (LH + 1)];
__device__ int                g_csr_src[BB * RR];
__device__ float              g_m[BB * NH * DD];
__device__ float              g_cb[BB * NH];
__device__ float              g_logits[BB * NH * RR];
__device__ float              g_y[BB * NH * DD];
__device__ float              g_ctxp[4][BB * UU];

__device__ __forceinline__ unsigned ford(float f) {
    unsigned u = __float_as_uint(f);
    return (u & 0x80000000u) ? ~u : (u | 0x80000000u);
}

// packed fp32x2 FMA (sm_100+): acc = a*b + acc, two lanes per instruction
__device__ __forceinline__ void ffma2(unsigned long long& acc,
                                      unsigned long long a, unsigned long long b) {
    asm("fma.rn.f32x2 %0, %1, %2, %0;" : "+l"(acc) : "l"(a), "l"(b));
}
__device__ __forceinline__ unsigned long long pk2(float x, float y) {
    unsigned long long r;
    asm("mov.b64 %0, {%1, %2};" : "=l"(r) : "f"(x), "f"(y));
    return r;
}
__device__ __forceinline__ float lo32(unsigned long long v) {
    return __uint_as_float((unsigned)v);
}
__device__ __forceinline__ float hi32(unsigned long long v) {
    return __uint_as_float((unsigned)(v >> 32));
}

// ---------------- K0: init accumulators (must run every replay) -----------
__global__ void k_init() {
    int i = blockIdx.x * blockDim.x + threadIdx.x;
    if (i < BB * LL) g_imp[i] = 0.f;
    if (i < BB * LH) g_nodekey[i] = 0ull;
}

// ---------------- importance = column sums, diag removed ------------------
__global__ void k_importance(const float* __restrict__ sc) {
    int b = blockIdx.z, h = blockIdx.y, chunk = blockIdx.x;
    int j0 = threadIdx.x * 4;
    const float* base = sc + (((size_t)b * HH + h) * LL + (size_t)chunk * 64) * LL;
    int i0 = chunk * 64;
    float a0 = 0.f, a1 = 0.f, a2 = 0.f, a3 = 0.f;
#pragma unroll 4
    for (int i = 0; i < 64; i++) {
        float4 v = *(const float4*)(base + (size_t)i * LL + j0);
        int gi = i0 + i;
        if (gi == j0)     v.x = 0.f;
        if (gi == j0 + 1) v.y = 0.f;
        if (gi == j0 + 2) v.z = 0.f;
        if (gi == j0 + 3) v.w = 0.f;
        a0 += v.x; a1 += v.y; a2 += v.z; a3 += v.w;
    }
    float* ip = g_imp + b * LL + j0;
    atomicAdd(ip + 0, a0); atomicAdd(ip + 1, a1);
    atomicAdd(ip + 2, a2); atomicAdd(ip + 3, a3);
}

// ---------------- per-token inverse L2 norms -------------------------------
__global__ void k_invnorm(const float* __restrict__ hid) {
    int warp = threadIdx.x >> 5, lane = threadIdx.x & 31;
    int row = blockIdx.x * 8 + warp;
    int b = blockIdx.y;
    const float4* p = (const float4*)(hid + ((size_t)b * LL + row) * DD);
    float s = 0.f;
#pragma unroll
    for (int it = 0; it < 6; it++) {
        float4 v = p[lane + it * 32];
        s += v.x * v.x + v.y * v.y + v.z * v.z + v.w * v.w;
    }
    for (int off = 16; off; off >>= 1) s += __shfl_xor_sync(0xffffffffu, s, off);
    if (lane == 0) g_invn[b * LL + row] = rsqrtf(s);
}

// ---------------- top-K -> unpreserved idx (ascending) ---------------------
// Rank-by-count with index tiebreak == lax.top_k; ballot-based compaction.
__global__ void k_topk() {
    int b = blockIdx.x, t = threadIdx.x;
    __shared__ __align__(16) unsigned long long keys[LL];
    __shared__ int wsum[16];
    float v = g_imp[b * LL + t];
    unsigned long long key =
        ((unsigned long long)ford(v) << 32) | (unsigned)(0xFFFFFFFFu - t);
    keys[t] = key;
    __syncthreads();
    int rank = 0;
    const ulonglong2* k2 = (const ulonglong2*)keys;
#pragma unroll 8
    for (int x = 0; x < LL / 2; x++) {
        ulonglong2 kk = k2[x];
        rank += (kk.x > key) + (kk.y > key);
    }
    int unp = (rank >= KP) ? 1 : 0;
    unsigned bal = __ballot_sync(0xffffffffu, unp);
    int lane = t & 31, wp = t >> 5;
    if (lane == 0) wsum[wp] = __popc(bal);
    __syncthreads();
    if (unp) {
        int base = 0;
        for (int w = 0; w < wp; w++) base += wsum[w];
        int pos = base + __popc(bal & ((1u << lane) - 1));
        g_unp[b * RR + pos] = t;
    }
}

// ---------------- cosine-sim GEMM + row max/argmax -------------------------
// 64x64 tile, 256 threads, 4x4 micro-tile in packed fp32x2 (exact fp32 fma
// per element — rank decisions identical to scalar). Row argmax via atomicMax.
__global__ void k_sim(const float* __restrict__ hid) {
    int b = blockIdx.z, i0 = blockIdx.y * 64, j0 = blockIdx.x * 64;
    __shared__ __align__(16) float As[16][68];
    __shared__ __align__(16) float Bs[16][68];
    int tid = threadIdx.x;
    int tx = tid & 15, ty = tid >> 4;
    int lrow = tid >> 2, lseg = tid & 3;
    const float* base = hid + (size_t)b * LL * DD;
    float ia = g_invn[b * LL + 2 * (i0 + lrow)];
    float ib = g_invn[b * LL + 2 * (j0 + lrow) + 1];
    const float* arow = base + (size_t)(2 * (i0 + lrow)) * DD + lseg * 4;
    const float* brow = base + (size_t)(2 * (j0 + lrow) + 1) * DD + lseg * 4;

    // acc2[p][q]: p=0 packs rows (4ty, 4ty+1), p=1 packs rows (4ty+2, 4ty+3)
    unsigned long long acc2[2][4];
#pragma unroll
    for (int p = 0; p < 2; p++)
#pragma unroll
        for (int q = 0; q < 4; q++) acc2[p][q] = 0ull;

    for (int k0 = 0; k0 < DD; k0 += 16) {
        float4 av = *(const float4*)(arow + k0);
        float4 bv = *(const float4*)(brow + k0);
        __syncthreads();
        As[lseg * 4 + 0][lrow] = av.x * ia;
        As[lseg * 4 + 1][lrow] = av.y * ia;
        As[lseg * 4 + 2][lrow] = av.z * ia;
        As[lseg * 4 + 3][lrow] = av.w * ia;
        Bs[lseg * 4 + 0][lrow] = bv.x * ib;
        Bs[lseg * 4 + 1][lrow] = bv.y * ib;
        Bs[lseg * 4 + 2][lrow] = bv.z * ib;
        Bs[lseg * 4 + 3][lrow] = bv.w * ib;
        __syncthreads();
#pragma unroll
        for (int kk = 0; kk < 16; kk++) {
            ulonglong2 ap = *(const ulonglong2*)&As[kk][ty * 4];  // (a0,a1),(a2,a3)
            float4 c4 = *(const float4*)&Bs[kk][tx * 4];
            unsigned long long c0 = pk2(c4.x, c4.x);
            unsigned long long c1 = pk2(c4.y, c4.y);
            unsigned long long c2 = pk2(c4.z, c4.z);
            unsigned long long c3 = pk2(c4.w, c4.w);
            ffma2(acc2[0][0], ap.x, c0); ffma2(acc2[1][0], ap.y, c0);
            ffma2(acc2[0][1], ap.x, c1); ffma2(acc2[1][1], ap.y, c1);
            ffma2(acc2[0][2], ap.x, c2); ffma2(acc2[1][2], ap.y, c2);
            ffma2(acc2[0][3], ap.x, c3); ffma2(acc2[1][3], ap.y, c3);
        }
    }
    // per-row max/argmax (tie -> smaller j, matching jnp.argmax)
#pragma unroll
    for (int r = 0; r < 4; r++) {
        int p = r >> 1;
        float v0, v1, v2, v3;
        if (r & 1) {
            v0 = hi32(acc2[p][0]); v1 = hi32(acc2[p][1]);
            v2 = hi32(acc2[p][2]); v3 = hi32(acc2[p][3]);
        } else {
            v0 = lo32(acc2[p][0]); v1 = lo32(acc2[p][1]);
            v2 = lo32(acc2[p][2]); v3 = lo32(acc2[p][3]);
        }
        float best = v0; int bc = 0;
        if (v1 > best) { best = v1; bc = 1; }
        if (v2 > best) { best = v2; bc = 2; }
        if (v3 > best) { best = v3; bc = 3; }
        int j = j0 + tx * 4 + bc;
        unsigned long long key =
            ((unsigned long long)ford(best) << 32) | (unsigned)(255 - j);
        for (int off = 8; off; off >>= 1) {
            unsigned long long o = __shfl_xor_sync(0xffffffffu, key, off);
            if (o > key) key = o;
        }
        if (tx == 0) atomicMax(&g_nodekey[b * LH + i0 + ty * 4 + r], key);
    }
}

// ---------------- edge argsort + CSR inverse map ---------------------------
// rank<128 -> src (build dst->src CSR lists in smem), else unm.
__global__ void k_edges() {
    int b = blockIdx.x, i = threadIdx.x;
    __shared__ __align__(16) unsigned long long ek[LH];
    __shared__ int scnt[LH];
    __shared__ int soff[LH];
    __shared__ int scur[LH];
    unsigned long long nk = g_nodekey[b * LH + i];
    int nidx = 255 - (int)(unsigned)(nk & 0xFFFFFFFFull);
    unsigned long long key = (nk & 0xFFFFFFFF00000000ull) | (unsigned)(255 - i);
    ek[i] = key;
    scnt[i] = 0;
    scur[i] = 0;
    __syncthreads();
    int rank = 0;
    const ulonglong2* k2 = (const ulonglong2*)ek;
#pragma unroll 8
    for (int x = 0; x < LH / 2; x++) {
        ulonglong2 kk = k2[x];
        rank += (kk.x > key) + (kk.y > key);
    }
    bool issrc = (rank < RR);
    if (issrc) atomicAdd(&scnt[nidx], 1);
    else g_unm[b * RR + (rank - RR)] = i;
    __syncthreads();
    int off = 0;
    for (int x = 0; x < i; x++) off += scnt[x];
    soff[i] = off;
    g_csr_off[b * (LH + 1) + i] = off;
    if (i == 0) g_csr_off[b * (LH + 1) + LH] = RR;
    __syncthreads();
    if (issrc) {
        int slot = atomicAdd(&scur[nidx], 1);
        g_csr_src[b * RR + soff[nidx] + slot] = i;
    }
}

// ---------------- assemble: class + unm copies -----------------------------
__global__ void k_copy(const float* __restrict__ hid, float* __restrict__ out) {
    int b = blockIdx.y, v = blockIdx.x;                  // 0..128
    int srow = (v == 0) ? 0 : 2 * g_unm[b * RR + (v - 1)];
    const float4* s = (const float4*)(hid + ((size_t)b * LL + srow) * DD);
    float4* d = (float4*)(out + ((size_t)b * OT + v) * DD);
    d[threadIdx.x] = s[threadIdx.x];
}

// ---------------- merged dst tokens via CSR gather (no atomics) ------------
__global__ void k_merge2(const float* __restrict__ hid, float* __restrict__ out) {
    int b = blockIdx.y, j = blockIdx.x;                  // 0..255
    int o0 = g_csr_off[b * (LH + 1) + j];
    int o1 = g_csr_off[b * (LH + 1) + j + 1];
    int d0 = threadIdx.x * 4;
    const float* dx = hid + ((size_t)b * LL + 2 * j + 1) * DD + d0;
    float4 a = *(const float4*)dx;
    for (int p = o0; p < o1; p++) {
        int s = g_csr_src[b * RR + p];
        float4 v = *(const float4*)(hid + ((size_t)b * LL + 2 * s) * DD + d0);
        a.x += v.x; a.y += v.y; a.z += v.z; a.w += v.w;
    }
    float inv = 1.0f / (float)(1 + (o1 - o0));
    a.x *= inv; a.y *= inv; a.z *= inv; a.w *= inv;
    *(float4*)(out + ((size_t)b * OT + 129 + j) * DD + d0) = a;
}

// ---------------- attention: q_h + m_h + cbias fused, grid (6,16) ----------
__global__ void k_qm(const float* __restrict__ hid, const float* __restrict__ Wq,
                     const float* __restrict__ bq, const float* __restrict__ Wk,
                     const float* __restrict__ bk) {
    int h = blockIdx.x, b = blockIdx.y, t = threadIdx.x;     // 256 threads
    __shared__ float cls[DD];
    __shared__ float qp[4][HD];
    __shared__ float sq[HD];
    __shared__ float sp[HD];
    cls[t] = hid[(size_t)b * LL * DD + t];
    cls[t + 256] = hid[(size_t)b * LL * DD + 256 + t];
    cls[t + 512] = hid[(size_t)b * LL * DD + 512 + t];
    __syncthreads();
    // stage 1: q_h[u] = bq + cls . Wq[:, h*64+u], k split 4 ways
    {
        int u = t & 63, kq = t >> 6;
        float p = 0.f;
        const float* wcol = Wq + (size_t)(h * HD + u);
#pragma unroll 4
        for (int k = kq * 192; k < kq * 192 + 192; k++)
            p += cls[k] * wcol[(size_t)k * UU];
        qp[kq][u] = p;
    }
    __syncthreads();
    if (t < HD) {
        float q = bq[h * HD + t] + qp[0][t] + qp[1][t] + qp[2][t] + qp[3][t];
        sq[t] = q;
        sp[t] = q * bk[h * HD + t];
    }
    __syncthreads();
    // stage 2: m[row] = Wk[row, h*64:h*64+64] . q_h, rows t, t+256, t+512
#pragma unroll
    for (int rr = 0; rr < 3; rr++) {
        int row = t + rr * 256;
        const float* wrow = Wk + (size_t)row * UU + h * HD;
        float acc = 0.f;
#pragma unroll
        for (int u = 0; u < HD; u += 4) {
            float4 wv = *(const float4*)(wrow + u);
            acc += wv.x * sq[u] + wv.y * sq[u + 1] + wv.z * sq[u + 2] + wv.w * sq[u + 3];
        }
        g_m[((size_t)b * NH + h) * DD + row] = acc;
    }
    if (t == 0) {
        float c = 0.f;
        for (int u = 0; u < HD; u++) c += sp[u];
        g_cb[b * NH + h] = c;
    }
}

// logits[b,h,t] = (x_t . m_bh + cbias) / 8      one warp per (b,t)
__global__ void k_logits(const float* __restrict__ hid) {
    int w = (blockIdx.x * blockDim.x + threadIdx.x) >> 5;
    int lane = threadIdx.x & 31;
    if (w >= BB * RR) return;
    int b = w >> 7, t = w & 127;
    int row = g_unp[b * RR + t];
    const float* x = hid + ((size_t)b * LL + row) * DD;
    const float* m = g_m + (size_t)b * NH * DD;
    float acc[NH] = {};
    for (int k = lane; k < DD; k += 32) {
        float xv = x[k];
#pragma unroll
        for (int h = 0; h < NH; h++) acc[h] += xv * m[h * DD + k];
    }
#pragma unroll
    for (int h = 0; h < NH; h++)
        for (int off = 16; off; off >>= 1) acc[h] += __shfl_xor_sync(0xffffffffu, acc[h], off);
    if (lane == 0) {
#pragma unroll
        for (int h = 0; h < NH; h++)
            g_logits[((size_t)b * NH + h) * RR + t] = (acc[h] + g_cb[b * NH + h]) * 0.125f;
    }
}

// softmax over 128 keys, then y[b,h,:] = sum_t w_t * x_t   grid (6,16), 256 thr
__global__ void k_smax_y(const float* __restrict__ hid) {
    int h = blockIdx.x, b = blockIdx.y, t = threadIdx.x;
    __shared__ float w[RR];
    __shared__ int su[RR];
    __shared__ float red[8];
    if (t < RR) {
        w[t] = g_logits[((size_t)b * NH + h) * RR + t];
        su[t] = g_unp[b * RR + t];
    }
    __syncthreads();
    if (t < RR) {
        float m = w[t];
        for (int off = 16; off; off >>= 1) m = fmaxf(m, __shfl_xor_sync(0xffffffffu, m, off));
        if ((t & 31) == 0) red[t >> 5] = m;
    }
    __syncthreads();
    float mx = fmaxf(fmaxf(red[0], red[1]), fmaxf(red[2], red[3]));
    float e = 0.f;
    if (t < RR) e = expf(w[t] - mx);
    float s = e;
    for (int off = 16; off; off >>= 1) s += __shfl_xor_sync(0xffffffffu, s, off);
    if (t < RR && (t & 31) == 0) red[4 + (t >> 5)] = s;
    __syncthreads();
    float tot = red[4] + red[5] + red[6] + red[7];
    if (t < RR) w[t] = e / tot;
    __syncthreads();
    for (int d = t; d < DD; d += 256) {
        float acc = 0.f;
#pragma unroll 4
        for (int tt = 0; tt < RR; tt++)
            acc += w[tt] * hid[((size_t)b * LL + su[tt]) * DD + d];
        g_y[((size_t)b * NH + h) * DD + d] = acc;
    }
}

// ctx partials: grid (16, 4), 384 threads; chunk c covers 192 of the 768 d's.
__global__ void k_ctx(const float* __restrict__ Wv, const float* __restrict__ bv) {
    int b = blockIdx.x, c = blockIdx.y, u = threadIdx.x;
    __shared__ float sy[NH * 192];
    for (int i = u; i < NH * 192; i += UU) {
        int h = i / 192, dd = i % 192;
        sy[i] = g_y[((size_t)b * NH + h) * DD + c * 192 + dd];
    }
    __syncthreads();
    int h = u >> 6;
    float acc = (c == 0) ? bv[u] : 0.f;
    const float* wv = Wv + (size_t)(c * 192) * UU + u;
#pragma unroll 4
    for (int dd = 0; dd < 192; dd++) acc += sy[h * 192 + dd] * wv[(size_t)dd * UU];
    g_ctxp[c][b * UU + u] = acc;
}

// new_token: grid (16, 6), 128 threads; sums 4 ctx partials, then GEMV.
__global__ void k_newtok(const float* __restrict__ Wo, const float* __restrict__ bo,
                         float* __restrict__ out) {
    int b = blockIdx.x, seg = blockIdx.y, t = threadIdx.x;
    __shared__ float sc[UU];
    for (int i = t; i < UU; i += 128)
        sc[i] = g_ctxp[0][b * UU + i] + g_ctxp[1][b * UU + i] +
                g_ctxp[2][b * UU + i] + g_ctxp[3][b * UU + i];
    __syncthreads();
    int d = seg * 128 + t;
    float acc = bo[d];
#pragma unroll 4
    for (int u = 0; u < UU; u++) acc += sc[u] * Wo[(size_t)u * DD + d];
    out[((size_t)b * OT + 385) * DD + d] = acc;
}

// ---------------- launch ----------------------------------------------------
extern "C" void kernel_launch(void* const* d_in, const int* in_sizes, int n_in,
                              void* d_out, int out_size) {
    (void)in_sizes; (void)n_in; (void)out_size;
    const float* hid = (const float*)d_in[0];
    const float* sc  = (const float*)d_in[1];
    const float* Wq  = (const float*)d_in[2];
    const float* bq  = (const float*)d_in[3];
    const float* Wk  = (const float*)d_in[4];
    const float* bk  = (const float*)d_in[5];
    const float* Wv  = (const float*)d_in[6];
    const float* bv  = (const float*)d_in[7];
    const float* Wo  = (const float*)d_in[8];
    const float* bo  = (const float*)d_in[9];
    float* out = (float*)d_out;

    k_init<<<32, 256>>>();
    k_importance<<<dim3(8, HH, BB), 128>>>(sc);
    k_invnorm<<<dim3(64, BB), 256>>>(hid);
    k_topk<<<BB, 512>>>();
    k_sim<<<dim3(4, 4, BB), 256>>>(hid);
    k_edges<<<BB, 256>>>();
    k_copy<<<dim3(129, BB), 192>>>(hid, out);
    k_merge2<<<dim3(LH, BB), 192>>>(hid, out);
    k_qm<<<dim3(NH, BB), 256>>>(hid, Wq, bq, Wk, bk);
    k_logits<<<256, 256>>>(hid);
    k_smax_y<<<dim3(NH, BB), 256>>>(hid);
    k_ctx<<<dim3(BB, 4), 384>>>(Wv, bv);
    k_newtok<<<dim3(BB, 6), 128>>>(Wo, bo, out);
}